// round 17
// baseline (speedup 1.0000x reference)
#include <cuda_runtime.h>
#include <cuda_fp16.h>
#include <stdint.h>

// Problem constants
#define NUM_STEPS 25
#define BATCH     4096
#define NIN       784
#define NHID      1000
#define NOUT      10
#define MTOT      (NUM_STEPS * BATCH)   // 102400
#define BETA      0.95f
#define THRESH    1.0f

// Layer-1 flag window per step (validated round 13/16).
#define DELTA  5e-5f
// Layer-2 flag window per step: covers w2-lo subnormal residual (<=3e-5
// worst case) + accumulation-order deviation (~3e-7 rms).
#define DELTA2 5e-5f

// Scratch (device globals; no runtime allocation allowed)
__device__ float     g_cur1[(size_t)MTOT * NHID];
__device__ uint32_t  g_maskT[(size_t)32 * MTOT];    // spk1 bits, [word][t*B+b]
__device__ float     g_cur2[(size_t)MTOT * NOUT];
__device__ uint32_t  g_flag[BATCH * 32];
__device__ uint32_t  g_flag2[(BATCH * NOUT) / 32];  // layer-2 chain flags
__device__ __half    g_xh[(size_t)MTOT * NIN];
__device__ __half    g_xl[(size_t)MTOT * NIN];
__device__ __half    g_wh[(size_t)1024 * NIN];
__device__ __half    g_wl[(size_t)1024 * NIN];

static __device__ __forceinline__ uint32_t smem_u32(const void* p) {
    uint32_t a;
    asm("{ .reg .u64 t; cvta.to.shared.u64 t, %1; cvt.u32.u64 %0, t; }"
        : "=r"(a) : "l"(p));
    return a;
}

#define LDMX4(r0, r1, r2, r3, a) \
    asm volatile("ldmatrix.sync.aligned.m8n8.x4.shared.b16 {%0,%1,%2,%3}, [%4];" \
                 : "=r"(r0), "=r"(r1), "=r"(r2), "=r"(r3) : "r"(a))

#define MMA_F16(c, a, b) \
    asm volatile("mma.sync.aligned.m16n8k16.row.col.f32.f16.f16.f32 " \
                 "{%0,%1,%2,%3}, {%4,%5,%6,%7}, {%8,%9}, {%0,%1,%2,%3};" \
                 : "+f"((c)[0]), "+f"((c)[1]), "+f"((c)[2]), "+f"((c)[3]) \
                 : "r"((a)[0]), "r"((a)[1]), "r"((a)[2]), "r"((a)[3]), \
                   "r"((b)[0]), "r"((b)[1]))

// fp16x2 from two mask bits (b, b+1): each 1.0h or 0.0h
static __device__ __forceinline__ uint32_t bits2h2(uint32_t w, int b) {
    const uint32_t lo = ((w >> b) & 1u) * 0x3C00u;
    const uint32_t hi = ((w >> (b + 1)) & 1u) * 0x3C00u;
    return lo | (hi << 16);
}

// ---------------------------------------------------------------------------
// Split kernels (vectorized): v = vh + vl (fp16 hi + fp16 residual).
// ---------------------------------------------------------------------------
__global__ void __launch_bounds__(256)
splitx_kernel(const float* __restrict__ X)
{
    const int id = blockIdx.x * 256 + threadIdx.x;   // < MTOT*196
    const int m  = id / 196;
    const int k  = (id - m * 196) * 4;
    const float4 v = *(const float4*)(X + (size_t)m * NIN + k);
    __half h0 = __float2half_rn(v.x), h1 = __float2half_rn(v.y);
    __half h2 = __float2half_rn(v.z), h3 = __float2half_rn(v.w);
    __half l0 = __float2half_rn(v.x - __half2float(h0));
    __half l1 = __float2half_rn(v.y - __half2float(h1));
    __half l2 = __float2half_rn(v.z - __half2float(h2));
    __half l3 = __float2half_rn(v.w - __half2float(h3));
    __half2 hh[2] = {__halves2half2(h0, h1), __halves2half2(h2, h3)};
    __half2 ll[2] = {__halves2half2(l0, l1), __halves2half2(l2, l3)};
    *(uint2*)(g_xh + (size_t)m * NIN + k) = *(uint2*)hh;
    *(uint2*)(g_xl + (size_t)m * NIN + k) = *(uint2*)ll;
}

__global__ void __launch_bounds__(256)
splitw_kernel(const float* __restrict__ W1)
{
    const int id = blockIdx.x * 256 + threadIdx.x;   // < 1024*196
    const int h  = id / 196;
    const int k  = (id - h * 196) * 4;
    float4 v = make_float4(0.f, 0.f, 0.f, 0.f);
    if (h < NHID) v = *(const float4*)(W1 + (size_t)h * NIN + k);
    __half h0 = __float2half_rn(v.x), h1 = __float2half_rn(v.y);
    __half h2 = __float2half_rn(v.z), h3 = __float2half_rn(v.w);
    __half l0 = __float2half_rn(v.x - __half2float(h0));
    __half l1 = __float2half_rn(v.y - __half2float(h1));
    __half l2 = __float2half_rn(v.z - __half2float(h2));
    __half l3 = __float2half_rn(v.w - __half2float(h3));
    __half2 hh[2] = {__halves2half2(h0, h1), __halves2half2(h2, h3)};
    __half2 ll[2] = {__halves2half2(l0, l1), __halves2half2(l2, l3)};
    *(uint2*)(g_wh + (size_t)h * NIN + k) = *(uint2*)hh;
    *(uint2*)(g_wl + (size_t)h * NIN + k) = *(uint2*)ll;
}

// ---------------------------------------------------------------------------
// gemm1 on HMMA fp16 (round-16 proven): cur1 ~= Xh@Wh^T + Xh@Wl^T + Xl@Wh^T
// + b1. CTA 128x128, 8 warps (2x4), warp 64x32, 49 k-steps of 16.
// Double-buffered static smem, register prefetch, one sync per step.
// ---------------------------------------------------------------------------
#define TILE_BYTES 6144        // 128 * 48
#define STAGE_BYTES 24576
#define NKS 49

__global__ void __launch_bounds__(256)
gemm1t_kernel(const float* __restrict__ b1)
{
    __shared__ __align__(16) char smem[2][STAGE_BYTES];

    const int tid    = threadIdx.x;
    const int wid    = tid >> 5;
    const int lane   = tid & 31;
    const int bm     = blockIdx.y * 128;
    const int bn     = blockIdx.x * 128;
    const int warp_m = (wid >> 2) * 64;
    const int warp_n = (wid & 3) * 32;

    const int lrow = tid >> 1;
    const int lc   = tid & 1;
    const __half* gxh = g_xh + (size_t)(bm + lrow) * NIN + lc * 8;
    const __half* gxl = g_xl + (size_t)(bm + lrow) * NIN + lc * 8;
    const __half* gwh = g_wh + (size_t)(bn + lrow) * NIN + lc * 8;
    const __half* gwl = g_wl + (size_t)(bn + lrow) * NIN + lc * 8;
    const int soff = lrow * 48 + lc * 16;

    const uint32_t sb = smem_u32(smem);
    const uint32_t aoff = (uint32_t)((warp_m + (lane & 15)) * 48 + (lane >> 4) * 16);
    const uint32_t boff0 = (uint32_t)((warp_n + ((lane >> 4) << 3) + (lane & 7)) * 48
                                      + ((lane >> 3) & 1) * 16);
    const uint32_t boff1 = boff0 + 16 * 48;

    float acc[4][4][4];
#pragma unroll
    for (int i = 0; i < 4; i++)
#pragma unroll
        for (int j = 0; j < 4; j++)
#pragma unroll
            for (int r = 0; r < 4; r++) acc[i][j][r] = 0.f;

    uint4 p0, p1, p2, p3;
    p0 = *(const uint4*)(gxh);
    p1 = *(const uint4*)(gxl);
    p2 = *(const uint4*)(gwh);
    p3 = *(const uint4*)(gwl);
    {
        char* s = smem[0] + soff;
        *(uint4*)(s)                  = p0;
        *(uint4*)(s + TILE_BYTES)     = p1;
        *(uint4*)(s + 2 * TILE_BYTES) = p2;
        *(uint4*)(s + 3 * TILE_BYTES) = p3;
    }
    __syncthreads();

#pragma unroll 1
    for (int kt = 0; kt < NKS; kt++) {
        const int cur = kt & 1;

        if (kt + 1 < NKS) {
            const int ko = (kt + 1) * 16;
            p0 = *(const uint4*)(gxh + ko);
            p1 = *(const uint4*)(gxl + ko);
            p2 = *(const uint4*)(gwh + ko);
            p3 = *(const uint4*)(gwl + ko);
        }

        const uint32_t st = sb + (uint32_t)cur * STAGE_BYTES;

        uint32_t bh[8], bl[8];
        LDMX4(bh[0], bh[1], bh[2], bh[3], st + 2 * TILE_BYTES + boff0);
        LDMX4(bh[4], bh[5], bh[6], bh[7], st + 2 * TILE_BYTES + boff1);
        LDMX4(bl[0], bl[1], bl[2], bl[3], st + 3 * TILE_BYTES + boff0);
        LDMX4(bl[4], bl[5], bl[6], bl[7], st + 3 * TILE_BYTES + boff1);

#pragma unroll
        for (int mi = 0; mi < 4; mi++) {
            uint32_t ah[4], al[4];
            LDMX4(ah[0], ah[1], ah[2], ah[3], st + aoff + mi * (16 * 48));
            LDMX4(al[0], al[1], al[2], al[3], st + TILE_BYTES + aoff + mi * (16 * 48));
#pragma unroll
            for (int nj = 0; nj < 4; nj++) {
                uint32_t bhf[2] = {bh[nj * 2], bh[nj * 2 + 1]};
                uint32_t blf[2] = {bl[nj * 2], bl[nj * 2 + 1]};
                MMA_F16(acc[mi][nj], ah, bhf);   // hh
                MMA_F16(acc[mi][nj], ah, blf);   // hl
                MMA_F16(acc[mi][nj], al, bhf);   // lh
            }
        }

        if (kt + 1 < NKS) {
            char* s = smem[(kt + 1) & 1] + soff;
            *(uint4*)(s)                  = p0;
            *(uint4*)(s + TILE_BYTES)     = p1;
            *(uint4*)(s + 2 * TILE_BYTES) = p2;
            *(uint4*)(s + 3 * TILE_BYTES) = p3;
            __syncthreads();
        }
    }

    const int m0 = bm + warp_m + (lane >> 2);
    const int n0 = bn + warp_n + (lane & 3) * 2;
#pragma unroll
    for (int mi = 0; mi < 4; mi++) {
#pragma unroll
        for (int nj = 0; nj < 4; nj++) {
            const int n = n0 + nj * 8;
            if (n < NHID - 1) {
                const float bx = __ldg(&b1[n]);
                const float by = __ldg(&b1[n + 1]);
                const int mA = m0 + mi * 16;
                float2 v0, v1;
                v0.x = __fadd_rn(acc[mi][nj][0], bx);
                v0.y = __fadd_rn(acc[mi][nj][1], by);
                v1.x = __fadd_rn(acc[mi][nj][2], bx);
                v1.y = __fadd_rn(acc[mi][nj][3], by);
                *(float2*)&g_cur1[(size_t)mA * NHID + n] = v0;
                *(float2*)&g_cur1[(size_t)(mA + 8) * NHID + n] = v1;
            }
        }
    }
}

// ---------------------------------------------------------------------------
// flagrec: preload 25 cur1 values, recurrence with error radius; writes
// provisional spike mask + per-chain flag bits.
// ---------------------------------------------------------------------------
__global__ void __launch_bounds__(256)
flagrec_kernel()
{
    const int warp  = (blockIdx.x * blockDim.x + threadIdx.x) >> 5;
    const int lane  = threadIdx.x & 31;
    const int chunk = warp & 31;
    const int b     = warp >> 5;
    if (b >= BATCH) return;

    const int h = chunk * 32 + lane;
    const bool valid = (h < NHID);

    float cbuf[NUM_STEPS];
#pragma unroll
    for (int t = 0; t < NUM_STEPS; t++)
        cbuf[t] = valid ? g_cur1[((size_t)t * BATCH + b) * NHID + h] : -1.f;

    float mem = 0.f, e = 0.f;
    bool flg = false;
#pragma unroll
    for (int t = 0; t < NUM_STEPS; t++) {
        const float c = cbuf[t];
        const float rst = (mem > THRESH) ? THRESH : 0.f;
        mem = __fsub_rn(__fadd_rn(__fmul_rn(BETA, mem), c), rst);
        e = BETA * e + DELTA + 2e-7f * (fabsf(mem) + 2.f);
        flg = flg || (valid && fabsf(mem - THRESH) <= e);
        const uint32_t w = __ballot_sync(0xffffffffu, mem > THRESH);
        if (lane == 0)
            g_maskT[(size_t)chunk * MTOT + (size_t)t * BATCH + b] = w;
    }
    const uint32_t f = __ballot_sync(0xffffffffu, flg);
    if (lane == 0) g_flag[b * 32 + chunk] = f;
}

// ---------------------------------------------------------------------------
// Fixup: exact unfused chain for flagged (b,h); patch mask bits atomically.
// ---------------------------------------------------------------------------
#define XLD 785

__global__ void __launch_bounds__(256)
fixup_kernel(const float* __restrict__ X, const float* __restrict__ W1,
             const float* __restrict__ b1)
{
    extern __shared__ float xs[];
    __shared__ unsigned short list[1024];
    __shared__ int cnt;

    const int b   = blockIdx.x;
    const int tid = threadIdx.x;
    if (tid == 0) cnt = 0;
    __syncthreads();

    for (int h = tid; h < NHID; h += 256) {
        if ((g_flag[b * 32 + (h >> 5)] >> (h & 31)) & 1u) {
            const int idx = atomicAdd(&cnt, 1);
            list[idx] = (unsigned short)h;
        }
    }
    __syncthreads();

    const int nf = cnt;
    if (nf == 0) return;

    for (int i = tid; i < NUM_STEPS * NIN; i += 256) {
        const int t = i / NIN, k = i - t * NIN;
        xs[t * XLD + k] = X[((size_t)t * BATCH + b) * NIN + k];
    }
    __syncthreads();

    const int warpid = tid >> 5;
    const int lane   = tid & 31;

    for (int u = warpid; u < nf; u += 8) {
        const int h = (int)list[u];
        const float* wrow = W1 + (size_t)h * NIN;

        float dotv = 0.f;
        if (lane < NUM_STEPS) {
            const float* xr = xs + lane * XLD;
            float acc = 0.f;
#pragma unroll 8
            for (int k = 0; k < NIN; k++)
                acc = __fadd_rn(acc, __fmul_rn(xr[k], __ldg(wrow + k)));
            dotv = __fadd_rn(acc, __ldg(&b1[h]));
        }

        float mem = 0.f;
        uint32_t myspk = 0;
#pragma unroll
        for (int t = 0; t < NUM_STEPS; t++) {
            const float c = __shfl_sync(0xffffffffu, dotv, t);
            const float rst = (mem > THRESH) ? THRESH : 0.f;
            mem = __fsub_rn(__fadd_rn(__fmul_rn(BETA, mem), c), rst);
            if (lane == t) myspk = (mem > THRESH) ? 1u : 0u;
        }

        if (lane < NUM_STEPS) {
            uint32_t* wp = &g_maskT[(size_t)(h >> 5) * MTOT +
                                    (size_t)lane * BATCH + b];
            const uint32_t bit = 1u << (h & 31);
            if (myspk) atomicOr(wp, bit);
            else       atomicAnd(wp, ~bit);
        }
    }
}

// ---------------------------------------------------------------------------
// gemm2h: cur2 ~= spk1 @ (W2h + W2l)^T + b2 on HMMA. A-fragments synthesized
// in-register from the spike bitmask (bit -> 1.0h); B = W2 fp16 hi/lo staged
// in smem (k-step 48B-row layout). spk*wh products exact; certification
// (flag2/fixup2) covers the wl residual + accumulation order.
// Grid: 800 CTAs x 8 warps; warp handles one m16 tile, K = 1024 (64 ksteps).
// ---------------------------------------------------------------------------
#define G2_PROD_BYTES (64 * 16 * 48)   // 49152 per product
#define G2_SMEM (2 * G2_PROD_BYTES)    // 98304

__global__ void __launch_bounds__(256)
gemm2h_kernel(const float* __restrict__ W2, const float* __restrict__ b2)
{
    extern __shared__ __align__(16) char bsm[];
    const uint32_t sb = smem_u32(bsm);
    const int tid  = threadIdx.x;
    const int wid  = tid >> 5;
    const int lane = tid & 31;

    // stage W2 hi/lo into per-kstep 48B-row layout (n=16 rows, k padded 1024)
    for (int i = tid; i < 16 * 1024; i += 256) {
        const int n = i >> 10, k = i & 1023;
        const float v = (n < NOUT && k < NHID) ? W2[n * NHID + k] : 0.f;
        const __half vh = __float2half_rn(v);
        const __half vl = __float2half_rn(v - __half2float(vh));
        const int ks = k >> 4, kk = k & 15;
        const int off = ks * 768 + n * 48 + (kk >> 3) * 16 + (kk & 7) * 2;
        *(__half*)(bsm + off)                 = vh;
        *(__half*)(bsm + G2_PROD_BYTES + off) = vl;
    }
    __syncthreads();

    const int m0 = (blockIdx.x * 8 + wid) * 16;      // m-tile base
    const int r0 = m0 + (lane >> 2);
    const int r1 = r0 + 8;
    const int cbase = 2 * (lane & 3);

    const uint32_t boff = (uint32_t)((((lane >> 4) << 3) + (lane & 7)) * 48
                                     + ((lane >> 3) & 1) * 16);

    float acc0[4] = {0.f, 0.f, 0.f, 0.f};   // nj=0 (cols 0-7)
    float acc1[4] = {0.f, 0.f, 0.f, 0.f};   // nj=1 (cols 8-15)

    uint32_t w0 = 0, w1 = 0;
#pragma unroll 1
    for (int ks = 0; ks < 64; ks++) {
        if ((ks & 1) == 0) {
            const size_t wrow = (size_t)(ks >> 1) * MTOT;
            w0 = g_maskT[wrow + r0];
            w1 = g_maskT[wrow + r1];
        }
        const int bb = ((ks & 1) << 4) + cbase;

        uint32_t a[4];
        a[0] = bits2h2(w0, bb);
        a[1] = bits2h2(w1, bb);
        a[2] = bits2h2(w0, bb + 8);
        a[3] = bits2h2(w1, bb + 8);

        uint32_t bh[4], bl[4];
        LDMX4(bh[0], bh[1], bh[2], bh[3], sb + ks * 768 + boff);
        LDMX4(bl[0], bl[1], bl[2], bl[3], sb + G2_PROD_BYTES + ks * 768 + boff);

        uint32_t bh0[2] = {bh[0], bh[1]}, bh1[2] = {bh[2], bh[3]};
        uint32_t bl0[2] = {bl[0], bl[1]}, bl1[2] = {bl[2], bl[3]};
        MMA_F16(acc0, a, bh0);
        MMA_F16(acc0, a, bl0);
        MMA_F16(acc1, a, bh1);
        MMA_F16(acc1, a, bl1);
    }

    // epilogue: cur2[m][o] = acc + b2[o], o < 10
    {
        const float bx = __ldg(&b2[cbase]);
        const float by = __ldg(&b2[cbase + 1]);
        float2 v0, v1;
        v0.x = __fadd_rn(acc0[0], bx);
        v0.y = __fadd_rn(acc0[1], by);
        v1.x = __fadd_rn(acc0[2], bx);
        v1.y = __fadd_rn(acc0[3], by);
        *(float2*)&g_cur2[(size_t)r0 * NOUT + cbase] = v0;
        *(float2*)&g_cur2[(size_t)r1 * NOUT + cbase] = v1;
    }
    if (cbase == 0) {   // nj=1 cols 8,9 only
        const float bx = __ldg(&b2[8]);
        const float by = __ldg(&b2[9]);
        float2 v0, v1;
        v0.x = __fadd_rn(acc1[0], bx);
        v0.y = __fadd_rn(acc1[1], by);
        v1.x = __fadd_rn(acc1[2], bx);
        v1.y = __fadd_rn(acc1[3], by);
        *(float2*)&g_cur2[(size_t)r0 * NOUT + 8] = v0;
        *(float2*)&g_cur2[(size_t)r1 * NOUT + 8] = v1;
    }
}

// ---------------------------------------------------------------------------
// flag2rec2: layer-2 recurrence on approx cur2 with error radius; writes
// outputs [spk_rec | mem_rec] + flags for uncertain chains.
// ---------------------------------------------------------------------------
__global__ void __launch_bounds__(256)
flag2rec2_kernel(float* __restrict__ out)
{
    const int idx  = blockIdx.x * 256 + threadIdx.x;   // b*10+o, < 40960
    const int lane = threadIdx.x & 31;

    float cbuf[NUM_STEPS];
#pragma unroll
    for (int t = 0; t < NUM_STEPS; t++)
        cbuf[t] = g_cur2[(size_t)t * (BATCH * NOUT) + idx];

    float mem = 0.f, e = 0.f;
    bool flg = false;
#pragma unroll
    for (int t = 0; t < NUM_STEPS; t++) {
        const float c = cbuf[t];
        const float rst = (mem > THRESH) ? THRESH : 0.f;
        mem = __fsub_rn(__fadd_rn(__fmul_rn(BETA, mem), c), rst);
        e = BETA * e + DELTA2 + 2e-7f * (fabsf(mem) + 2.f);
        flg = flg || (fabsf(mem - THRESH) <= e);
        const float spk = (mem > THRESH) ? 1.f : 0.f;
        out[(size_t)t * (BATCH * NOUT) + idx] = spk;
        out[(size_t)NUM_STEPS * BATCH * NOUT + (size_t)t * (BATCH * NOUT) + idx] = mem;
    }
    const uint32_t f = __ballot_sync(0xffffffffu, flg);
    if (lane == 0) g_flag2[idx >> 5] = f;
}

// ---------------------------------------------------------------------------
// fixup2: for flagged (b,o), recompute EXACT cur2 chain (ascending-bit fadd
// over spike mask + bias; the round-16-validated exact-skip logic) and the
// exact recurrence; overwrite outputs.
// ---------------------------------------------------------------------------
__global__ void __launch_bounds__(256)
fixup2_kernel(const float* __restrict__ W2, const float* __restrict__ b2,
              float* __restrict__ out)
{
    const int idx = blockIdx.x * 256 + threadIdx.x;   // < 40960
    if (!((g_flag2[idx >> 5] >> (idx & 31)) & 1u)) return;

    const int b = idx / NOUT;
    const int o = idx - b * NOUT;
    const float bias = __ldg(&b2[o]);

    float mem = 0.f;
#pragma unroll 1
    for (int t = 0; t < NUM_STEPS; t++) {
        float acc = 0.f;
#pragma unroll 1
        for (int wd = 0; wd < 32; wd++) {
            uint32_t w = g_maskT[(size_t)wd * MTOT + (size_t)t * BATCH + b];
            while (w) {
                const int bit = __ffs(w) - 1;
                w &= w - 1;
                acc = __fadd_rn(acc, __ldg(&W2[o * NHID + wd * 32 + bit]));
            }
        }
        const float c = __fadd_rn(acc, bias);
        const float rst = (mem > THRESH) ? THRESH : 0.f;
        mem = __fsub_rn(__fadd_rn(__fmul_rn(BETA, mem), c), rst);
        const float spk = (mem > THRESH) ? 1.f : 0.f;
        out[(size_t)t * (BATCH * NOUT) + idx] = spk;
        out[(size_t)NUM_STEPS * BATCH * NOUT + (size_t)t * (BATCH * NOUT) + idx] = mem;
    }
}

// ---------------------------------------------------------------------------
extern "C" void kernel_launch(void* const* d_in, const int* in_sizes, int n_in,
                              void* d_out, int out_size)
{
    const float* x  = (const float*)d_in[0];
    const float* W1 = (const float*)d_in[1];
    const float* b1 = (const float*)d_in[2];
    const float* W2 = (const float*)d_in[3];
    const float* b2 = (const float*)d_in[4];
    float* out = (float*)d_out;

    const int xs_bytes = NUM_STEPS * XLD * (int)sizeof(float);
    cudaFuncSetAttribute(fixup_kernel,
                         cudaFuncAttributeMaxDynamicSharedMemorySize, xs_bytes);
    cudaFuncSetAttribute(gemm2h_kernel,
                         cudaFuncAttributeMaxDynamicSharedMemorySize, G2_SMEM);

    splitx_kernel<<<(MTOT * 196) / 256, 256>>>(x);
    splitw_kernel<<<(1024 * 196) / 256, 256>>>(W1);

    dim3 g1(8, MTOT / 128);
    gemm1t_kernel<<<g1, 256>>>(b1);

    flagrec_kernel<<<(BATCH * 32) / 8, 256>>>();

    fixup_kernel<<<BATCH, 256, xs_bytes>>>(x, W1, b1);

    gemm2h_kernel<<<MTOT / 128, 256, G2_SMEM>>>(W2, b2);

    flag2rec2_kernel<<<(BATCH * NOUT) / 256, 256>>>(out);

    fixup2_kernel<<<(BATCH * NOUT) / 256, 256>>>(W2, b2, out);
}